// round 2
// baseline (speedup 1.0000x reference)
#include <cuda_runtime.h>
#include <cuda_bf16.h>
#include <mma.h>
#include <math.h>

using namespace nvcuda;

#define B_   4
#define L_   2048
#define D_   2048
#define H_   16
#define HD_  128
#define BL_  (B_*L_)          // 8192
#define SM_SCALE 0.08838834764831845f   // 1/sqrt(128)

// ---------------- scratch (device globals; no allocation allowed) ----------------
__device__ float g_Q[BL_*D_];   // [b,h,l,d] after proj(+norm+rope+scale)
__device__ float g_K[BL_*D_];   // [b,h,l,d]
__device__ float g_V[BL_*D_];   // [b,h,l,d]
__device__ float g_A[BL_*D_];   // attention out, [b,l,h,d] = [8192,2048]

// ================================================================================
// TF32 GEMM:  C[m,n] = sum_k A[m,k] * W[n,k]   (A:[M,K] row-major, W:[N,K] row-major)
// mode 0: C row-major [M, 2048]
// mode 1: write tile to [b,h,l,d] layout (head-transposed), BN=128 == one head
// ================================================================================
#define GBM 128
#define GBN 128
#define GBK 32
#define GLD 40   // BK + 8 pad

__global__ __launch_bounds__(256) void gemm_tf32_kernel(
    const float* __restrict__ A, const float* __restrict__ W,
    float* __restrict__ C, int K, int mode)
{
    __shared__ float As[GBM*GLD];
    __shared__ float Bs[GBN*GLD];

    const int tid  = threadIdx.x;
    const int warp = tid >> 5;
    const int wm   = warp >> 2;     // 0..1
    const int wn   = warp & 3;      // 0..3
    const int rowBase = blockIdx.y * GBM;
    const int colBase = blockIdx.x * GBN;

    wmma::fragment<wmma::accumulator,16,16,8,float> cf[4][2];
    #pragma unroll
    for (int i=0;i<4;i++)
        #pragma unroll
        for (int j=0;j<2;j++)
            wmma::fill_fragment(cf[i][j], 0.0f);

    for (int k0 = 0; k0 < K; k0 += GBK) {
        // load A & W tiles (128x32 each), convert to tf32 in smem
        #pragma unroll
        for (int p=0;p<4;p++){
            int idx = tid + p*256;      // 0..1023 float4 slots
            int r   = idx >> 3;         // row 0..127
            int c4  = idx & 7;          // float4 col 0..7
            float4 va = *(const float4*)(A + (size_t)(rowBase+r)*K + k0 + c4*4);
            float* da = As + r*GLD + c4*4;
            da[0]=wmma::__float_to_tf32(va.x); da[1]=wmma::__float_to_tf32(va.y);
            da[2]=wmma::__float_to_tf32(va.z); da[3]=wmma::__float_to_tf32(va.w);
            float4 vb = *(const float4*)(W + (size_t)(colBase+r)*K + k0 + c4*4);
            float* db = Bs + r*GLD + c4*4;
            db[0]=wmma::__float_to_tf32(vb.x); db[1]=wmma::__float_to_tf32(vb.y);
            db[2]=wmma::__float_to_tf32(vb.z); db[3]=wmma::__float_to_tf32(vb.w);
        }
        __syncthreads();

        #pragma unroll
        for (int kk=0; kk<4; kk++) {
            wmma::fragment<wmma::matrix_a,16,16,8,wmma::precision::tf32,wmma::row_major> af[4];
            #pragma unroll
            for (int i=0;i<4;i++)
                wmma::load_matrix_sync(af[i], As + (wm*64 + i*16)*GLD + kk*8, GLD);
            wmma::fragment<wmma::matrix_b,16,16,8,wmma::precision::tf32,wmma::col_major> bf[2];
            #pragma unroll
            for (int j=0;j<2;j++)
                wmma::load_matrix_sync(bf[j], Bs + (wn*32 + j*16)*GLD + kk*8, GLD);
            #pragma unroll
            for (int i=0;i<4;i++)
                #pragma unroll
                for (int j=0;j<2;j++)
                    wmma::mma_sync(cf[i][j], af[i], bf[j], cf[i][j]);
        }
        __syncthreads();
    }

    if (mode == 0) {
        #pragma unroll
        for (int i=0;i<4;i++){
            int m = rowBase + wm*64 + i*16;
            #pragma unroll
            for (int j=0;j<2;j++){
                int n = colBase + wn*32 + j*16;
                wmma::store_matrix_sync(C + (size_t)m*D_ + n, cf[i][j], D_, wmma::mem_row_major);
            }
        }
    } else {
        // head-transposed: out[((b*H + h)*L + l)*HD + d], h = blockIdx.x
        const int hh = blockIdx.x;
        #pragma unroll
        for (int i=0;i<4;i++){
            int m = rowBase + wm*64 + i*16;
            int b = m >> 11;            // L_ = 2048
            int l = m & 2047;
            float* dst = C + (((size_t)b*H_ + hh)*L_ + l)*HD_ + wn*32;
            #pragma unroll
            for (int j=0;j<2;j++)
                wmma::store_matrix_sync(dst + j*16, cf[i][j], HD_, wmma::mem_row_major);
        }
    }
}

// ================================================================================
// In-place per-head RMSNorm + RoPE on g_Q / g_K ([b,h,l,d]); Q also gets SM_SCALE.
// One warp per (b,h,l) head vector; lane owns 4 consecutive d (float4).
// ================================================================================
__global__ __launch_bounds__(256) void normrope_kernel(
    float* __restrict__ Q, float* __restrict__ Kx,
    const float* __restrict__ cosq, const float* __restrict__ sinq,
    const float* __restrict__ cosk, const float* __restrict__ sink,
    const float* __restrict__ qg,   const float* __restrict__ kg)
{
    const unsigned FULL = 0xffffffffu;
    int gw   = (blockIdx.x*256 + threadIdx.x) >> 5;   // 0 .. B*H*L-1 (== (b,h,l) in order)
    int lane = threadIdx.x & 31;
    int l    = gw % L_;
    int b    = gw / (H_*L_);
    int d0   = lane*4;
    size_t base  = (size_t)gw * HD_;
    size_t cbase = ((size_t)b*L_ + l)*HD_ + d0;
    float sgn = (lane < 16) ? -1.0f : 1.0f;

    // ---- Q ----
    {
        float4 v = *(const float4*)(Q + base + d0);
        float ss = v.x*v.x + v.y*v.y + v.z*v.z + v.w*v.w;
        #pragma unroll
        for (int o=16;o;o>>=1) ss += __shfl_xor_sync(FULL, ss, o);
        float rs = rsqrtf(ss*(1.0f/128.0f) + 1e-6f);
        float4 g = *(const float4*)(qg + d0);
        float4 n; n.x=v.x*rs*g.x; n.y=v.y*rs*g.y; n.z=v.z*rs*g.z; n.w=v.w*rs*g.w;
        float4 p;
        p.x=__shfl_xor_sync(FULL,n.x,16); p.y=__shfl_xor_sync(FULL,n.y,16);
        p.z=__shfl_xor_sync(FULL,n.z,16); p.w=__shfl_xor_sync(FULL,n.w,16);
        float4 c = *(const float4*)(cosq + cbase);
        float4 s = *(const float4*)(sinq + cbase);
        float4 o4;
        o4.x = (n.x*c.x + sgn*p.x*s.x) * SM_SCALE;
        o4.y = (n.y*c.y + sgn*p.y*s.y) * SM_SCALE;
        o4.z = (n.z*c.z + sgn*p.z*s.z) * SM_SCALE;
        o4.w = (n.w*c.w + sgn*p.w*s.w) * SM_SCALE;
        *(float4*)(Q + base + d0) = o4;
    }
    // ---- K ----
    {
        float4 v = *(const float4*)(Kx + base + d0);
        float ss = v.x*v.x + v.y*v.y + v.z*v.z + v.w*v.w;
        #pragma unroll
        for (int o=16;o;o>>=1) ss += __shfl_xor_sync(FULL, ss, o);
        float rs = rsqrtf(ss*(1.0f/128.0f) + 1e-6f);
        float4 g = *(const float4*)(kg + d0);
        float4 n; n.x=v.x*rs*g.x; n.y=v.y*rs*g.y; n.z=v.z*rs*g.z; n.w=v.w*rs*g.w;
        float4 p;
        p.x=__shfl_xor_sync(FULL,n.x,16); p.y=__shfl_xor_sync(FULL,n.y,16);
        p.z=__shfl_xor_sync(FULL,n.z,16); p.w=__shfl_xor_sync(FULL,n.w,16);
        float4 c = *(const float4*)(cosk + cbase);
        float4 s = *(const float4*)(sink + cbase);
        float4 o4;
        o4.x = n.x*c.x + sgn*p.x*s.x;
        o4.y = n.y*c.y + sgn*p.y*s.y;
        o4.z = n.z*c.z + sgn*p.z*s.z;
        o4.w = n.w*c.w + sgn*p.w*s.w;
        *(float4*)(Kx + base + d0) = o4;
    }
}

// ================================================================================
// Flash attention (non-causal), tf32 wmma, online softmax through smem.
// CTA: 256 threads (8 warps), BQ=64 q-rows, BKT=64 k-cols per iter, hd=128.
// grid = (L/64, B*H)
// ================================================================================
#define QLD 136   // 128 + 8
#define SLD 72    // 64 + 8
#define OLDM 132  // 128 + 4
#define FL_SMEM_FLOATS (3*64*QLD + 64*SLD + 2*64*OLDM + 3*64 + 64*4)
#define FL_SMEM_BYTES  (FL_SMEM_FLOATS*4)   // 192256

__global__ __launch_bounds__(256) void flash_kernel(
    const float* __restrict__ Q, const float* __restrict__ Kt,
    const float* __restrict__ Vt, float* __restrict__ Out)
{
    extern __shared__ float sm[];
    float* Qs   = sm;                  // 64 x QLD
    float* Ks   = Qs  + 64*QLD;        // 64 x QLD
    float* Vs   = Ks  + 64*QLD;        // 64 x QLD
    float* Ss   = Vs  + 64*QLD;        // 64 x SLD  (scores, then P in tf32)
    float* Os   = Ss  + 64*SLD;        // 64 x OLDM (running O, fp32)
    float* Ot   = Os  + 64*OLDM;       // 64 x OLDM (fresh P*V)
    float* mrow = Ot  + 64*OLDM;       // 64
    float* lrow = mrow + 64;           // 64
    float* arow = lrow + 64;           // 64
    float* psum = arow + 64;           // 64 x 4

    const int tid = threadIdx.x;
    const int w   = tid >> 5;
    const int wr  = w >> 1;            // 0..3  (16-row slice)
    const int wc  = w & 1;             // 0..1
    const int bh  = blockIdx.y;
    const int qt  = blockIdx.x;
    const int b   = bh >> 4;
    const int h   = bh & 15;

    const float* Qg = Q  + ((size_t)bh*L_ + qt*64)*HD_;
    const float* Kg = Kt + (size_t)bh*L_*HD_;
    const float* Vg = Vt + (size_t)bh*L_*HD_;

    // load Q tile (already scaled), tf32-convert
    #pragma unroll
    for (int p=0;p<8;p++){
        int idx = tid + p*256;
        int r = idx >> 5, c4 = idx & 31;
        float4 v = *(const float4*)(Qg + r*HD_ + c4*4);
        float* d = Qs + r*QLD + c4*4;
        d[0]=wmma::__float_to_tf32(v.x); d[1]=wmma::__float_to_tf32(v.y);
        d[2]=wmma::__float_to_tf32(v.z); d[3]=wmma::__float_to_tf32(v.w);
    }
    if (tid < 64) { mrow[tid] = -1e30f; lrow[tid] = 0.0f; }
    #pragma unroll
    for (int p=0;p<33;p++){ int idx = tid + p*256; Os[idx] = 0.0f; }   // 33*256 == 64*OLDM
    __syncthreads();

    for (int kt=0; kt<L_/64; kt++) {
        // load K & V tiles, tf32-convert
        const float* Kgt = Kg + (size_t)kt*64*HD_;
        const float* Vgt = Vg + (size_t)kt*64*HD_;
        #pragma unroll
        for (int p=0;p<8;p++){
            int idx = tid + p*256;
            int r = idx >> 5, c4 = idx & 31;
            float4 vk = *(const float4*)(Kgt + r*HD_ + c4*4);
            float* dk = Ks + r*QLD + c4*4;
            dk[0]=wmma::__float_to_tf32(vk.x); dk[1]=wmma::__float_to_tf32(vk.y);
            dk[2]=wmma::__float_to_tf32(vk.z); dk[3]=wmma::__float_to_tf32(vk.w);
            float4 vv = *(const float4*)(Vgt + r*HD_ + c4*4);
            float* dv = Vs + r*QLD + c4*4;
            dv[0]=wmma::__float_to_tf32(vv.x); dv[1]=wmma::__float_to_tf32(vv.y);
            dv[2]=wmma::__float_to_tf32(vv.z); dv[3]=wmma::__float_to_tf32(vv.w);
        }
        __syncthreads();

        // S = Q * K^T  (each warp: 16 rows x 32 cols)
        {
            wmma::fragment<wmma::accumulator,16,16,8,float> sc[2];
            wmma::fill_fragment(sc[0],0.0f); wmma::fill_fragment(sc[1],0.0f);
            #pragma unroll
            for (int ks=0; ks<16; ks++){
                wmma::fragment<wmma::matrix_a,16,16,8,wmma::precision::tf32,wmma::row_major> af;
                wmma::load_matrix_sync(af, Qs + (wr*16)*QLD + ks*8, QLD);
                #pragma unroll
                for (int j=0;j<2;j++){
                    wmma::fragment<wmma::matrix_b,16,16,8,wmma::precision::tf32,wmma::col_major> bf;
                    wmma::load_matrix_sync(bf, Ks + (wc*32 + j*16)*QLD + ks*8, QLD);
                    wmma::mma_sync(sc[j], af, bf, sc[j]);
                }
            }
            wmma::store_matrix_sync(Ss + (wr*16)*SLD + wc*32,      sc[0], SLD, wmma::mem_row_major);
            wmma::store_matrix_sync(Ss + (wr*16)*SLD + wc*32 + 16, sc[1], SLD, wmma::mem_row_major);
        }
        __syncthreads();

        // phase a: row max + alpha (one thread per row)
        if (tid < 64) {
            int r = tid;
            float mold = mrow[r];
            float mx = mold;
            const float* srow = Ss + r*SLD;
            #pragma unroll
            for (int c=0;c<64;c++) mx = fmaxf(mx, srow[c]);
            float al = __expf(mold - mx);
            mrow[r] = mx; arow[r] = al; lrow[r] *= al;
        }
        __syncthreads();

        // phase c: exp -> P (tf32), partial row sums; rescale Os by alpha
        {
            int r = tid >> 2, q = tid & 3;
            float mx = mrow[r];
            float s = 0.0f;
            float* srow = Ss + r*SLD + q*16;
            #pragma unroll
            for (int jj=0;jj<16;jj++){
                float pv = __expf(srow[jj] - mx);
                s += pv;
                srow[jj] = wmma::__float_to_tf32(pv);
            }
            psum[r*4 + q] = s;
            #pragma unroll
            for (int p2=0;p2<32;p2++){
                int idx = tid + p2*256;
                int ro = idx >> 7, co = idx & 127;
                Os[ro*OLDM + co] *= arow[ro];
            }
        }
        __syncthreads();

        // PV: each warp 16 rows x 64 cols
        {
            wmma::fragment<wmma::accumulator,16,16,8,float> oc[4];
            #pragma unroll
            for (int j=0;j<4;j++) wmma::fill_fragment(oc[j], 0.0f);
            #pragma unroll
            for (int ks=0; ks<8; ks++){
                wmma::fragment<wmma::matrix_a,16,16,8,wmma::precision::tf32,wmma::row_major> pf;
                wmma::load_matrix_sync(pf, Ss + (wr*16)*SLD + ks*8, SLD);
                #pragma unroll
                for (int j=0;j<4;j++){
                    wmma::fragment<wmma::matrix_b,16,16,8,wmma::precision::tf32,wmma::row_major> vf;
                    wmma::load_matrix_sync(vf, Vs + (ks*8)*QLD + wc*64 + j*16, QLD);
                    wmma::mma_sync(oc[j], pf, vf, oc[j]);
                }
            }
            #pragma unroll
            for (int j=0;j<4;j++)
                wmma::store_matrix_sync(Ot + (wr*16)*OLDM + wc*64 + j*16, oc[j], OLDM, wmma::mem_row_major);
        }
        __syncthreads();

        // merge: Os += Ot ; lrow += partial sums
        #pragma unroll
        for (int p2=0;p2<32;p2++){
            int idx = tid + p2*256;
            int ro = idx >> 7, co = idx & 127;
            Os[ro*OLDM + co] += Ot[ro*OLDM + co];
        }
        if (tid < 64)
            lrow[tid] += psum[tid*4] + psum[tid*4+1] + psum[tid*4+2] + psum[tid*4+3];
        __syncthreads();
    }

    // epilogue: normalize and write to [b,l,h,d]
    #pragma unroll
    for (int p2=0;p2<32;p2++){
        int idx = tid + p2*256;
        int r = idx >> 7, c = idx & 127;
        float o = Os[r*OLDM + c] / lrow[r];
        Out[ (((size_t)b*L_ + qt*64 + r)*H_ + h)*HD_ + c ] = o;
    }
}

// ================================================================================
extern "C" void kernel_launch(void* const* d_in, const int* in_sizes, int n_in,
                              void* d_out, int out_size)
{
    const float* x    = (const float*)d_in[0];
    const float* cosq = (const float*)d_in[1];
    const float* sinq = (const float*)d_in[2];
    const float* cosk = (const float*)d_in[3];
    const float* sink = (const float*)d_in[4];
    const float* Wq   = (const float*)d_in[5];
    const float* Wk   = (const float*)d_in[6];
    const float* Wv   = (const float*)d_in[7];
    const float* Wo   = (const float*)d_in[8];
    const float* qg   = (const float*)d_in[9];
    const float* kg   = (const float*)d_in[10];
    float* out = (float*)d_out;

    float *Qb, *Kb, *Vb, *Ab;
    cudaGetSymbolAddress((void**)&Qb, g_Q);
    cudaGetSymbolAddress((void**)&Kb, g_K);
    cudaGetSymbolAddress((void**)&Vb, g_V);
    cudaGetSymbolAddress((void**)&Ab, g_A);

    cudaFuncSetAttribute(flash_kernel, cudaFuncAttributeMaxDynamicSharedMemorySize,
                         FL_SMEM_BYTES);

    dim3 gg(D_/GBN, BL_/GBM);   // (16, 64)

    // QKV projections, writing directly head-transposed [b,h,l,d]
    gemm_tf32_kernel<<<gg, 256>>>(x, Wq, Qb, D_, 1);
    gemm_tf32_kernel<<<gg, 256>>>(x, Wk, Kb, D_, 1);
    gemm_tf32_kernel<<<gg, 256>>>(x, Wv, Vb, D_, 1);

    // in-place RMSNorm + RoPE (+ softmax scale folded into Q)
    normrope_kernel<<<(B_*H_*L_)/8, 256>>>(Qb, Kb, cosq, sinq, cosk, sink, qg, kg);

    // flash attention -> g_A in [b,l,h,d]
    flash_kernel<<<dim3(L_/64, B_*H_), 256, FL_SMEM_BYTES>>>(Qb, Kb, Vb, Ab);

    // output projection -> d_out
    gemm_tf32_kernel<<<gg, 256>>>(Ab, Wo, out, D_, 0);
}

// round 5
// speedup vs baseline: 1.2333x; 1.2333x over previous
#include <cuda_runtime.h>
#include <cuda_bf16.h>
#include <mma.h>
#include <math.h>
#include <stdint.h>

using namespace nvcuda;

#define B_   4
#define L_   2048
#define D_   2048
#define H_   16
#define HD_  128
#define BL_  (B_*L_)
#define SM_SCALE 0.08838834764831845f

__device__ float g_X[BL_*D_];
__device__ float g_Wr[4][D_*D_];
__device__ float g_Q[BL_*D_];
__device__ float g_K[BL_*D_];
__device__ float g_V[BL_*D_];
__device__ float g_A[BL_*D_];

// ---------------- helpers ----------------
__device__ __forceinline__ uint32_t smem_u32(const void* p){
    uint32_t a;
    asm("{ .reg .u64 t; cvta.to.shared.u64 t, %1; cvt.u32.u64 %0, t; }":"=r"(a):"l"(p));
    return a;
}
__device__ __forceinline__ void cpa16(uint32_t dst, const void* src){
    asm volatile("cp.async.cg.shared.global [%0], [%1], 16;"::"r"(dst),"l"(src):"memory");
}
#define CPA_COMMIT() asm volatile("cp.async.commit_group;":::"memory")
#define CPA_WAIT(N)  asm volatile("cp.async.wait_group %0;"::"n"(N):"memory")

extern __shared__ __align__(1024) char dynsm[];

// ---------------- tf32 pre-round ----------------
__global__ __launch_bounds__(256) void round_tf32_kernel(
    const float* __restrict__ s, float* __restrict__ d, int n)
{
    int i = (blockIdx.x*256 + threadIdx.x)*4;
    if (i < n){
        float4 v = *(const float4*)(s+i);
        v.x = wmma::__float_to_tf32(v.x); v.y = wmma::__float_to_tf32(v.y);
        v.z = wmma::__float_to_tf32(v.z); v.w = wmma::__float_to_tf32(v.w);
        *(float4*)(d+i) = v;
    }
}

// ================================================================================
// Pipelined tf32 wmma GEMM: C[m,n] = sum_k A[m,k]*W[n,k]
// BM=BN=128, BK=32, 3-stage cp.async, 8 warps (each 64x32 of C).
// mode 0: row-major C (no rounding).  mode 1: head-transposed [b,h,l,d], tf32-rounded.
// ================================================================================
#define GLD 36
#define GBK 32
#define KIT (D_/GBK)                 // 64
#define ASTG (128*GLD*4)             // 18432 bytes
#define STG  (2*ASTG)                // 36864
#define GSMEM (3*STG)                // 110592

__global__ __launch_bounds__(256,2) void gemm_pipe(
    const float* __restrict__ A, const float* __restrict__ W,
    float* __restrict__ C, int mode)
{
    float* fs = (float*)dynsm;
    const uint32_t smb = smem_u32(fs);
    const int tid  = threadIdx.x;
    const int warp = tid >> 5;
    const int wm   = warp >> 2;     // 0..1
    const int wn   = warp & 3;      // 0..3
    const int rowBase = blockIdx.y * 128;
    const int colBase = blockIdx.x * 128;

    wmma::fragment<wmma::accumulator,16,16,8,float> cf[4][2];
    #pragma unroll
    for (int i=0;i<4;i++)
        #pragma unroll
        for (int j=0;j<2;j++)
            wmma::fill_fragment(cf[i][j], 0.0f);

    auto load_stage = [&](int k){
        const int st = k % 3;
        const uint32_t sb = smb + (uint32_t)st*STG;
        const int k0 = k*GBK;
        #pragma unroll
        for (int c=0;c<8;c++){
            int idx = tid + c*256;          // 0..2047
            int row = idx >> 3;             // 0..255
            int c16 = idx & 7;              // float4 col
            if (row < 128){
                cpa16(sb + (uint32_t)(row*GLD + c16*4)*4,
                      A + (size_t)(rowBase+row)*D_ + k0 + c16*4);
            } else {
                int r2 = row - 128;
                cpa16(sb + ASTG + (uint32_t)(r2*GLD + c16*4)*4,
                      W + (size_t)(colBase+r2)*D_ + k0 + c16*4);
            }
        }
        CPA_COMMIT();
    };

    load_stage(0);
    load_stage(1);

    for (int k=0; k<KIT; k++){
        if (k+2 < KIT) load_stage(k+2);
        int rem = KIT-1-k;
        if (rem >= 2)      { CPA_WAIT(2); }
        else if (rem == 1) { CPA_WAIT(1); }
        else               { CPA_WAIT(0); }
        __syncthreads();

        const float* As = fs + (size_t)(k%3)*STG/4;
        const float* Bs = As + ASTG/4;
        #pragma unroll
        for (int kk=0; kk<4; kk++){
            wmma::fragment<wmma::matrix_a,16,16,8,wmma::precision::tf32,wmma::row_major> af[4];
            #pragma unroll
            for (int i=0;i<4;i++)
                wmma::load_matrix_sync(af[i], As + (wm*64 + i*16)*GLD + kk*8, GLD);
            wmma::fragment<wmma::matrix_b,16,16,8,wmma::precision::tf32,wmma::col_major> bf[2];
            #pragma unroll
            for (int j=0;j<2;j++)
                wmma::load_matrix_sync(bf[j], Bs + (wn*32 + j*16)*GLD + kk*8, GLD);
            #pragma unroll
            for (int i=0;i<4;i++)
                #pragma unroll
                for (int j=0;j<2;j++)
                    wmma::mma_sync(cf[i][j], af[i], bf[j], cf[i][j]);
        }
        __syncthreads();
    }

    if (mode == 0){
        #pragma unroll
        for (int i=0;i<4;i++){
            int m = rowBase + wm*64 + i*16;
            #pragma unroll
            for (int j=0;j<2;j++){
                int n = colBase + wn*32 + j*16;
                wmma::store_matrix_sync(C + (size_t)m*D_ + n, cf[i][j], D_, wmma::mem_row_major);
            }
        }
    } else {
        const int hh = blockIdx.x;
        #pragma unroll
        for (int i=0;i<4;i++){
            int m = rowBase + wm*64 + i*16;
            int b = m >> 11;
            int l = m & 2047;
            float* dst = C + (((size_t)b*H_ + hh)*L_ + l)*HD_ + wn*32;
            #pragma unroll
            for (int j=0;j<2;j++){
                #pragma unroll
                for (int e=0;e<cf[i][j].num_elements;e++)
                    cf[i][j].x[e] = wmma::__float_to_tf32(cf[i][j].x[e]);
                wmma::store_matrix_sync(dst + j*16, cf[i][j], HD_, wmma::mem_row_major);
            }
        }
    }
}

// ---------------- RMSNorm + RoPE (in place, tf32-rounded stores) ----------------
__global__ __launch_bounds__(256) void normrope_kernel(
    float* __restrict__ Q, float* __restrict__ Kx,
    const float* __restrict__ cosq, const float* __restrict__ sinq,
    const float* __restrict__ cosk, const float* __restrict__ sink,
    const float* __restrict__ qg,   const float* __restrict__ kg)
{
    const unsigned FULL = 0xffffffffu;
    int gw   = (blockIdx.x*256 + threadIdx.x) >> 5;
    int lane = threadIdx.x & 31;
    int l    = gw % L_;
    int b    = gw / (H_*L_);
    int d0   = lane*4;
    size_t base  = (size_t)gw * HD_;
    size_t cbase = ((size_t)b*L_ + l)*HD_ + d0;
    float sgn = (lane < 16) ? -1.0f : 1.0f;

    {
        float4 v = *(const float4*)(Q + base + d0);
        float ss = v.x*v.x + v.y*v.y + v.z*v.z + v.w*v.w;
        #pragma unroll
        for (int o=16;o;o>>=1) ss += __shfl_xor_sync(FULL, ss, o);
        float rs = rsqrtf(ss*(1.0f/128.0f) + 1e-6f);
        float4 g = *(const float4*)(qg + d0);
        float4 n; n.x=v.x*rs*g.x; n.y=v.y*rs*g.y; n.z=v.z*rs*g.z; n.w=v.w*rs*g.w;
        float4 p;
        p.x=__shfl_xor_sync(FULL,n.x,16); p.y=__shfl_xor_sync(FULL,n.y,16);
        p.z=__shfl_xor_sync(FULL,n.z,16); p.w=__shfl_xor_sync(FULL,n.w,16);
        float4 c = *(const float4*)(cosq + cbase);
        float4 s = *(const float4*)(sinq + cbase);
        float4 o4;
        o4.x = wmma::__float_to_tf32((n.x*c.x + sgn*p.x*s.x) * SM_SCALE);
        o4.y = wmma::__float_to_tf32((n.y*c.y + sgn*p.y*s.y) * SM_SCALE);
        o4.z = wmma::__float_to_tf32((n.z*c.z + sgn*p.z*s.z) * SM_SCALE);
        o4.w = wmma::__float_to_tf32((n.w*c.w + sgn*p.w*s.w) * SM_SCALE);
        *(float4*)(Q + base + d0) = o4;
    }
    {
        float4 v = *(const float4*)(Kx + base + d0);
        float ss = v.x*v.x + v.y*v.y + v.z*v.z + v.w*v.w;
        #pragma unroll
        for (int o=16;o;o>>=1) ss += __shfl_xor_sync(FULL, ss, o);
        float rs = rsqrtf(ss*(1.0f/128.0f) + 1e-6f);
        float4 g = *(const float4*)(kg + d0);
        float4 n; n.x=v.x*rs*g.x; n.y=v.y*rs*g.y; n.z=v.z*rs*g.z; n.w=v.w*rs*g.w;
        float4 p;
        p.x=__shfl_xor_sync(FULL,n.x,16); p.y=__shfl_xor_sync(FULL,n.y,16);
        p.z=__shfl_xor_sync(FULL,n.z,16); p.w=__shfl_xor_sync(FULL,n.w,16);
        float4 c = *(const float4*)(cosk + cbase);
        float4 s = *(const float4*)(sink + cbase);
        float4 o4;
        o4.x = wmma::__float_to_tf32(n.x*c.x + sgn*p.x*s.x);
        o4.y = wmma::__float_to_tf32(n.y*c.y + sgn*p.y*s.y);
        o4.z = wmma::__float_to_tf32(n.z*c.z + sgn*p.z*s.z);
        o4.w = wmma::__float_to_tf32(n.w*c.w + sgn*p.w*s.w);
        *(float4*)(Kx + base + d0) = o4;
    }
}

// ================================================================================
// flash2: BQ=128, 8 warps x 16 owned rows, warp-local softmax, O in fragments.
// K double-buffered cp.async, V single-buffered cp.async prefetch.
// ================================================================================
#define NIT  (L_/64)        // 32
#define FQLD 136
#define FKLD 136
#define FSLD 72
#define QS_F   (128*FQLD)                 // floats
#define KS_F   (64*FKLD)
#define FL_KS  QS_F
#define FL_VS  (FL_KS + 2*KS_F)
#define FL_SS  (FL_VS + KS_F)
#define FL_AT  (FL_SS + 8*16*FSLD)
#define FL_TOT (FL_AT + 8*256)
#define FL_BYTES (FL_TOT*4)               // 219136

__global__ __launch_bounds__(256) void flash2_kernel(
    const float* __restrict__ Q, const float* __restrict__ Kt,
    const float* __restrict__ Vt, float* __restrict__ Out)
{
    float* fs = (float*)dynsm;
    float* Qs = fs;
    float* Ks = fs + FL_KS;
    float* Vs = fs + FL_VS;
    const int tid = threadIdx.x, w = tid>>5, lane = tid&31;
    float* Ss = fs + FL_SS + w*16*FSLD;
    float* At = fs + FL_AT + w*256;
    const uint32_t ksb = smem_u32(Ks);
    const uint32_t vsb = smem_u32(Vs);

    const int bh = blockIdx.y, qt = blockIdx.x;
    const int b = bh >> 4, h = bh & 15;
    const float* Qg = Q  + ((size_t)bh*L_ + qt*128)*HD_;
    const float* Kg = Kt + (size_t)bh*L_*HD_;
    const float* Vg = Vt + (size_t)bh*L_*HD_;

    auto loadK = [&](int i, int stage){
        const float* src = Kg + (size_t)i*64*HD_;
        uint32_t base = ksb + (uint32_t)stage*(KS_F*4);
        #pragma unroll
        for (int p=0;p<8;p++){
            int idx = tid + p*256;
            int r = idx >> 5, c4 = idx & 31;
            cpa16(base + (uint32_t)(r*FKLD + c4*4)*4, src + r*HD_ + c4*4);
        }
        CPA_COMMIT();
    };
    auto loadV = [&](int i){
        const float* src = Vg + (size_t)i*64*HD_;
        #pragma unroll
        for (int p=0;p<8;p++){
            int idx = tid + p*256;
            int r = idx >> 5, c4 = idx & 31;
            cpa16(vsb + (uint32_t)(r*FKLD + c4*4)*4, src + r*HD_ + c4*4);
        }
        CPA_COMMIT();
    };

    loadK(0, 0);
    loadV(0);
    loadK(1, 1);

    // Q tile (normal loads; visible after first barrier)
    #pragma unroll
    for (int p=0;p<16;p++){
        int idx = tid + p*256;
        int r = idx >> 5, c4 = idx & 31;
        *(float4*)(Qs + r*FQLD + c4*4) = *(const float4*)(Qg + r*HD_ + c4*4);
    }

    const int myr  = lane >> 1;
    const int half = lane & 1;
    float mrow = -1e30f, lrow = 0.f;

    wmma::fragment<wmma::accumulator,16,16,8,float> oc[8];
    #pragma unroll
    for (int j=0;j<8;j++) wmma::fill_fragment(oc[j], 0.f);

    for (int i=0; i<NIT; i++){
        // wait for K[i]: groups committed after it = 2 (i<2), 3 (2<=i<=30), 2 (i=31)
        if (i < 2)       { CPA_WAIT(2); }
        else if (i < 31) { CPA_WAIT(3); }
        else             { CPA_WAIT(2); }
        __syncthreads();

        const float* Kst = Ks + (i&1)*KS_F;

        // S = Qrows x K^T (16x64 per warp)
        wmma::fragment<wmma::accumulator,16,16,8,float> sc[4];
        #pragma unroll
        for (int j=0;j<4;j++) wmma::fill_fragment(sc[j], 0.f);
        #pragma unroll
        for (int ka=0; ka<16; ka++){
            wmma::fragment<wmma::matrix_a,16,16,8,wmma::precision::tf32,wmma::row_major> af;
            wmma::load_matrix_sync(af, Qs + (w*16)*FQLD + ka*8, FQLD);
            #pragma unroll
            for (int j=0;j<4;j++){
                wmma::fragment<wmma::matrix_b,16,16,8,wmma::precision::tf32,wmma::col_major> bf;
                wmma::load_matrix_sync(bf, Kst + (j*16)*FKLD + ka*8, FKLD);
                wmma::mma_sync(sc[j], af, bf, sc[j]);
            }
        }
        __syncthreads();                 // all warps done reading K stage i&1
        if (i+2 < NIT) loadK(i+2, i&1);  // prefetch into freed stage

        #pragma unroll
        for (int j=0;j<4;j++)
            wmma::store_matrix_sync(Ss + j*16, sc[j], FSLD, wmma::mem_row_major);
        __syncwarp();

        // warp-local online softmax (lane pair per row)
        float* srow = Ss + myr*FSLD + half*32;
        float mx = mrow;
        #pragma unroll
        for (int c=0;c<32;c++) mx = fmaxf(mx, srow[c]);
        mx = fmaxf(mx, __shfl_xor_sync(0xffffffffu, mx, 1));
        float alpha = __expf(mrow - mx);
        float sum = 0.f;
        #pragma unroll
        for (int c=0;c<32;c++){
            float pv = __expf(srow[c] - mx);
            sum += pv;
            srow[c] = wmma::__float_to_tf32(pv);
        }
        sum += __shfl_xor_sync(0xffffffffu, sum, 1);
        lrow = lrow*alpha + sum;
        mrow = mx;

        // rescale O fragments via alpha broadcast tile
        #pragma unroll
        for (int c=0;c<8;c++) At[myr*16 + half*8 + c] = alpha;
        __syncwarp();
        wmma::fragment<wmma::accumulator,16,16,8,float> afr;
        wmma::load_matrix_sync(afr, At, 16, wmma::mem_row_major);
        #pragma unroll
        for (int j=0;j<8;j++)
            #pragma unroll
            for (int e=0;e<afr.num_elements;e++) oc[j].x[e] *= afr.x[e];

        // wait for V[i]: 1 newer group (K[i+2]) if it was issued, else 0
        if (i <= 29) { CPA_WAIT(1); }
        else         { CPA_WAIT(0); }
        __syncthreads();

        // O += P * V
        #pragma unroll
        for (int ka=0; ka<8; ka++){
            wmma::fragment<wmma::matrix_a,16,16,8,wmma::precision::tf32,wmma::row_major> pf;
            wmma::load_matrix_sync(pf, Ss + ka*8, FSLD);
            #pragma unroll
            for (int j=0;j<8;j++){
                wmma::fragment<wmma::matrix_b,16,16,8,wmma::precision::tf32,wmma::row_major> vf;
                wmma::load_matrix_sync(vf, Vs + (ka*8)*FKLD + j*16, FKLD);
                wmma::mma_sync(oc[j], pf, vf, oc[j]);
            }
        }
        __syncthreads();                 // all warps done reading Vs
        if (i+1 < NIT) loadV(i+1);
    }

    // epilogue: stage O through (free) Qs rows, normalize, tf32-round, write [b,l,h,d]
    float* Od = Qs + (w*16)*FQLD;
    #pragma unroll
    for (int j=0;j<8;j++)
        wmma::store_matrix_sync(Od + j*16, oc[j], FQLD, wmma::mem_row_major);
    __syncwarp();
    float rl = 1.f / lrow;
    int l = qt*128 + w*16 + myr;
    float* dst = Out + (((size_t)b*L_ + l)*H_ + h)*HD_ + half*64;
    const float* srcr = Od + myr*FQLD + half*64;
    #pragma unroll
    for (int c=0;c<16;c++){
        float4 v = *(const float4*)(srcr + c*4);
        v.x = wmma::__float_to_tf32(v.x*rl); v.y = wmma::__float_to_tf32(v.y*rl);
        v.z = wmma::__float_to_tf32(v.z*rl); v.w = wmma::__float_to_tf32(v.w*rl);
        *(float4*)(dst + c*4) = v;
    }
}

// ================================================================================
extern "C" void kernel_launch(void* const* d_in, const int* in_sizes, int n_in,
                              void* d_out, int out_size)
{
    const float* x    = (const float*)d_in[0];
    const float* cosq = (const float*)d_in[1];
    const float* sinq = (const float*)d_in[2];
    const float* cosk = (const float*)d_in[3];
    const float* sink = (const float*)d_in[4];
    const float* Wq   = (const float*)d_in[5];
    const float* Wk   = (const float*)d_in[6];
    const float* Wv   = (const float*)d_in[7];
    const float* Wo   = (const float*)d_in[8];
    const float* qg   = (const float*)d_in[9];
    const float* kg   = (const float*)d_in[10];
    float* out = (float*)d_out;

    float *Xr, *Wr, *Qb, *Kb, *Vb, *Ab;
    cudaGetSymbolAddress((void**)&Xr, g_X);
    cudaGetSymbolAddress((void**)&Wr, g_Wr);
    cudaGetSymbolAddress((void**)&Qb, g_Q);
    cudaGetSymbolAddress((void**)&Kb, g_K);
    cudaGetSymbolAddress((void**)&Vb, g_V);
    cudaGetSymbolAddress((void**)&Ab, g_A);

    cudaFuncSetAttribute(gemm_pipe, cudaFuncAttributeMaxDynamicSharedMemorySize, GSMEM);
    cudaFuncSetAttribute(flash2_kernel, cudaFuncAttributeMaxDynamicSharedMemorySize, FL_BYTES);

    // tf32 pre-round
    round_tf32_kernel<<<BL_*D_/1024, 256>>>(x,  Xr, BL_*D_);
    round_tf32_kernel<<<D_*D_/1024, 256>>>(Wq, Wr + 0*(size_t)D_*D_, D_*D_);
    round_tf32_kernel<<<D_*D_/1024, 256>>>(Wk, Wr + 1*(size_t)D_*D_, D_*D_);
    round_tf32_kernel<<<D_*D_/1024, 256>>>(Wv, Wr + 2*(size_t)D_*D_, D_*D_);
    round_tf32_kernel<<<D_*D_/1024, 256>>>(Wo, Wr + 3*(size_t)D_*D_, D_*D_);

    dim3 gg(D_/128, BL_/128);   // (16, 64)
    gemm_pipe<<<gg, 256, GSMEM>>>(Xr, Wr + 0*(size_t)D_*D_, Qb, 1);
    gemm_pipe<<<gg, 256, GSMEM>>>(Xr, Wr + 1*(size_t)D_*D_, Kb, 1);
    gemm_pipe<<<gg, 256, GSMEM>>>(Xr, Wr + 2*(size_t)D_*D_, Vb, 1);

    normrope_kernel<<<(B_*H_*L_)/8, 256>>>(Qb, Kb, cosq, sinq, cosk, sink, qg, kg);

    flash2_kernel<<<dim3(L_/128, B_*H_), 256, FL_BYTES>>>(Qb, Kb, Vb, Ab);

    gemm_pipe<<<gg, 256, GSMEM>>>(Ab, Wr + 3*(size_t)D_*D_, out, 0);
}

// round 6
// speedup vs baseline: 4.5322x; 3.6748x over previous
#include <cuda_runtime.h>
#include <cuda_fp16.h>
#include <mma.h>
#include <math.h>
#include <stdint.h>

using namespace nvcuda;

#define B_   4
#define L_   2048
#define D_   2048
#define H_   16
#define HD_  128
#define BL_  (B_*L_)
#define SM_SCALE 0.08838834764831845f

__device__ __half g_Xh[BL_*D_];
__device__ __half g_Wh[4][D_*D_];
__device__ __half g_Qh[BL_*D_];
__device__ __half g_Kh[BL_*D_];
__device__ __half g_Vh[BL_*D_];
__device__ __half g_Ah[BL_*D_];

// ---------------- helpers ----------------
__device__ __forceinline__ uint32_t smem_u32(const void* p){
    uint32_t a;
    asm("{ .reg .u64 t; cvta.to.shared.u64 t, %1; cvt.u32.u64 %0, t; }":"=r"(a):"l"(p));
    return a;
}
__device__ __forceinline__ void cpa16(uint32_t dst, const void* src){
    asm volatile("cp.async.cg.shared.global [%0], [%1], 16;"::"r"(dst),"l"(src):"memory");
}
#define CPA_COMMIT() asm volatile("cp.async.commit_group;":::"memory")
#define CPA_WAIT(N)  asm volatile("cp.async.wait_group %0;"::"n"(N):"memory")

extern __shared__ __align__(1024) char dynsm[];

// ---------------- fp32 -> fp16 convert ----------------
__global__ __launch_bounds__(256) void tohalf_kernel(
    const float* __restrict__ s, __half* __restrict__ d, int n)
{
    int i = (blockIdx.x*256 + threadIdx.x)*4;
    if (i < n){
        float4 v = *(const float4*)(s+i);
        __half2* dp = (__half2*)(d+i);
        dp[0] = __floats2half2_rn(v.x, v.y);
        dp[1] = __floats2half2_rn(v.z, v.w);
    }
}

// ================================================================================
// Pipelined fp16 wmma GEMM: C[m,n] = sum_k A[m,k]*W[n,k], fp32 accum.
// BM=BN=128, BK=64, 3-stage cp.async, 8 warps (each 64x32 of C), 2 CTAs/SM.
// mode 0: row-major fp32 C.   mode 1: head-transposed [b,h,l,d] half C.
// ================================================================================
#define GLDH 72
#define GBKH 64
#define KITH (D_/GBKH)               // 32
#define ASTGH (128*GLDH*2)           // 18432 bytes
#define STGH  (2*ASTGH)              // 36864
#define GSMEMH (3*STGH)              // 110592

__global__ __launch_bounds__(256,2) void gemm_h(
    const __half* __restrict__ A, const __half* __restrict__ W,
    void* __restrict__ Cv, int mode)
{
    __half* fs = (__half*)dynsm;
    const uint32_t smb = smem_u32(fs);
    const int tid  = threadIdx.x;
    const int warp = tid >> 5;
    const int wm   = warp >> 2;     // 0..1
    const int wn   = warp & 3;      // 0..3
    const int rowBase = blockIdx.y * 128;
    const int colBase = blockIdx.x * 128;

    wmma::fragment<wmma::accumulator,16,16,16,float> cf[4][2];
    #pragma unroll
    for (int i=0;i<4;i++)
        #pragma unroll
        for (int j=0;j<2;j++)
            wmma::fill_fragment(cf[i][j], 0.0f);

    auto load_stage = [&](int k){
        const int st = k % 3;
        const uint32_t sb = smb + (uint32_t)st*STGH;
        const int k0 = k*GBKH;
        #pragma unroll
        for (int c=0;c<8;c++){
            int idx = tid + c*256;          // 0..2047 chunks of 8 halves
            int row = idx >> 3;             // 0..255
            int c8  = (idx & 7)*8;          // half col
            if (row < 128){
                cpa16(sb + (uint32_t)(row*GLDH + c8)*2,
                      A + (size_t)(rowBase+row)*D_ + k0 + c8);
            } else {
                int r2 = row - 128;
                cpa16(sb + ASTGH + (uint32_t)(r2*GLDH + c8)*2,
                      W + (size_t)(colBase+r2)*D_ + k0 + c8);
            }
        }
        CPA_COMMIT();
    };

    load_stage(0);
    load_stage(1);

    for (int k=0; k<KITH; k++){
        if (k+2 < KITH) load_stage(k+2);
        int rem = KITH-1-k;
        if (rem >= 2)      { CPA_WAIT(2); }
        else if (rem == 1) { CPA_WAIT(1); }
        else               { CPA_WAIT(0); }
        __syncthreads();

        const __half* As = fs + (size_t)(k%3)*STGH/2;
        const __half* Bs = As + ASTGH/2;
        #pragma unroll
        for (int kk=0; kk<4; kk++){
            wmma::fragment<wmma::matrix_b,16,16,16,half,wmma::col_major> bf[2];
            #pragma unroll
            for (int j=0;j<2;j++)
                wmma::load_matrix_sync(bf[j], Bs + (wn*32 + j*16)*GLDH + kk*16, GLDH);
            #pragma unroll
            for (int i=0;i<4;i++){
                wmma::fragment<wmma::matrix_a,16,16,16,half,wmma::row_major> af;
                wmma::load_matrix_sync(af, As + (wm*64 + i*16)*GLDH + kk*16, GLDH);
                #pragma unroll
                for (int j=0;j<2;j++)
                    wmma::mma_sync(cf[i][j], af, bf[j], cf[i][j]);
            }
        }
        __syncthreads();
    }

    if (mode == 0){
        float* C = (float*)Cv;
        #pragma unroll
        for (int i=0;i<4;i++){
            int m = rowBase + wm*64 + i*16;
            #pragma unroll
            for (int j=0;j<2;j++){
                int n = colBase + wn*32 + j*16;
                wmma::store_matrix_sync(C + (size_t)m*D_ + n, cf[i][j], D_, wmma::mem_row_major);
            }
        }
    } else {
        // stage fp32 into (now free) pipeline smem, then convert+write half [b,h,l,d]
        float* stg = (float*)dynsm;       // 128 x 132 floats = 67584 B <= 110592
        #pragma unroll
        for (int i=0;i<4;i++)
            #pragma unroll
            for (int j=0;j<2;j++)
                wmma::store_matrix_sync(stg + (wm*64 + i*16)*132 + wn*32 + j*16,
                                        cf[i][j], 132, wmma::mem_row_major);
        __syncthreads();
        __half* C = (__half*)Cv;
        const int hh = blockIdx.x;
        #pragma unroll
        for (int p=0;p<8;p++){
            int idx = tid + p*256;        // 0..2047
            int r  = idx >> 4;            // 0..127
            int c8 = (idx & 15)*8;        // 0..120
            int m = rowBase + r;
            int b = m >> 11, l = m & 2047;
            const float* sr = stg + r*132 + c8;
            __half2 h0 = __floats2half2_rn(sr[0], sr[1]);
            __half2 h1 = __floats2half2_rn(sr[2], sr[3]);
            __half2 h2 = __floats2half2_rn(sr[4], sr[5]);
            __half2 h3 = __floats2half2_rn(sr[6], sr[7]);
            __half2* dst = (__half2*)(C + (((size_t)b*H_ + hh)*L_ + l)*HD_ + c8);
            dst[0]=h0; dst[1]=h1; dst[2]=h2; dst[3]=h3;
        }
    }
}

// ---------------- RMSNorm + RoPE (half in/out, fp32 math) ----------------
__global__ __launch_bounds__(256) void normrope_h_kernel(
    __half* __restrict__ Q, __half* __restrict__ Kx,
    const float* __restrict__ cosq, const float* __restrict__ sinq,
    const float* __restrict__ cosk, const float* __restrict__ sink,
    const float* __restrict__ qg,   const float* __restrict__ kg)
{
    const unsigned FULL = 0xffffffffu;
    int gw   = (blockIdx.x*256 + threadIdx.x) >> 5;
    int lane = threadIdx.x & 31;
    int l    = gw % L_;
    int b    = gw / (H_*L_);
    int d0   = lane*4;
    size_t base  = (size_t)gw * HD_;
    size_t cbase = ((size_t)b*L_ + l)*HD_ + d0;
    float sgn = (lane < 16) ? -1.0f : 1.0f;

    {
        const __half2* hp = (const __half2*)(Q + base + d0);
        float2 a0 = __half22float2(hp[0]), a1 = __half22float2(hp[1]);
        float4 v; v.x=a0.x; v.y=a0.y; v.z=a1.x; v.w=a1.y;
        float ss = v.x*v.x + v.y*v.y + v.z*v.z + v.w*v.w;
        #pragma unroll
        for (int o=16;o;o>>=1) ss += __shfl_xor_sync(FULL, ss, o);
        float rs = rsqrtf(ss*(1.0f/128.0f) + 1e-6f);
        float4 g = *(const float4*)(qg + d0);
        float4 n; n.x=v.x*rs*g.x; n.y=v.y*rs*g.y; n.z=v.z*rs*g.z; n.w=v.w*rs*g.w;
        float4 p;
        p.x=__shfl_xor_sync(FULL,n.x,16); p.y=__shfl_xor_sync(FULL,n.y,16);
        p.z=__shfl_xor_sync(FULL,n.z,16); p.w=__shfl_xor_sync(FULL,n.w,16);
        float4 c = *(const float4*)(cosq + cbase);
        float4 s = *(const float4*)(sinq + cbase);
        __half2* dp = (__half2*)(Q + base + d0);
        dp[0] = __floats2half2_rn((n.x*c.x + sgn*p.x*s.x)*SM_SCALE,
                                  (n.y*c.y + sgn*p.y*s.y)*SM_SCALE);
        dp[1] = __floats2half2_rn((n.z*c.z + sgn*p.z*s.z)*SM_SCALE,
                                  (n.w*c.w + sgn*p.w*s.w)*SM_SCALE);
    }
    {
        const __half2* hp = (const __half2*)(Kx + base + d0);
        float2 a0 = __half22float2(hp[0]), a1 = __half22float2(hp[1]);
        float4 v; v.x=a0.x; v.y=a0.y; v.z=a1.x; v.w=a1.y;
        float ss = v.x*v.x + v.y*v.y + v.z*v.z + v.w*v.w;
        #pragma unroll
        for (int o=16;o;o>>=1) ss += __shfl_xor_sync(FULL, ss, o);
        float rs = rsqrtf(ss*(1.0f/128.0f) + 1e-6f);
        float4 g = *(const float4*)(kg + d0);
        float4 n; n.x=v.x*rs*g.x; n.y=v.y*rs*g.y; n.z=v.z*rs*g.z; n.w=v.w*rs*g.w;
        float4 p;
        p.x=__shfl_xor_sync(FULL,n.x,16); p.y=__shfl_xor_sync(FULL,n.y,16);
        p.z=__shfl_xor_sync(FULL,n.z,16); p.w=__shfl_xor_sync(FULL,n.w,16);
        float4 c = *(const float4*)(cosk + cbase);
        float4 s = *(const float4*)(sink + cbase);
        __half2* dp = (__half2*)(Kx + base + d0);
        dp[0] = __floats2half2_rn(n.x*c.x + sgn*p.x*s.x,
                                  n.y*c.y + sgn*p.y*s.y);
        dp[1] = __floats2half2_rn(n.z*c.z + sgn*p.z*s.z,
                                  n.w*c.w + sgn*p.w*s.w);
    }
}

// ================================================================================
// flash fp16: BQ=128, 8 warps x 16 owned rows, warp-local softmax (fp32),
// O in fp32 fragments. K double-buffered cp.async, V single-buffered prefetch.
// ================================================================================
#define NIT  (L_/64)          // 32
#define FLDH 136              // half stride for Q/K/V tiles
#define FSLD 72               // float stride for S
#define FPLD 72               // half stride for P
// byte offsets in dynamic smem
#define QS_OFF 0
#define KS_OFF 34816                       // 128*136*2
#define VS_OFF (KS_OFF + 2*64*FLDH*2)      // +34816
#define SS_OFF (VS_OFF + 64*FLDH*2)        // +17408
#define PS_OFF (SS_OFF + 8*16*FSLD*4)      // +36864
#define AT_OFF (PS_OFF + 8*16*FPLD*2)      // +18432
#define FL_BYTES (AT_OFF + 8*256*4)        // 150528

__global__ __launch_bounds__(256) void flash_h_kernel(
    const __half* __restrict__ Q, const __half* __restrict__ Kt,
    const __half* __restrict__ Vt, __half* __restrict__ Out)
{
    __half* Qs = (__half*)(dynsm + QS_OFF);
    __half* Ks = (__half*)(dynsm + KS_OFF);
    __half* Vs = (__half*)(dynsm + VS_OFF);
    const int tid = threadIdx.x, w = tid>>5, lane = tid&31;
    float*  Ss = (float*)(dynsm + SS_OFF) + w*16*FSLD;
    __half* Ps = (__half*)(dynsm + PS_OFF) + w*16*FPLD;
    float*  At = (float*)(dynsm + AT_OFF) + w*256;
    const uint32_t ksb = smem_u32(Ks);
    const uint32_t vsb = smem_u32(Vs);
    const uint32_t qsb = smem_u32(Qs);

    const int bh = blockIdx.y, qt = blockIdx.x;
    const int b = bh >> 4, h = bh & 15;
    const __half* Qg = Q  + ((size_t)bh*L_ + qt*128)*HD_;
    const __half* Kg = Kt + (size_t)bh*L_*HD_;
    const __half* Vg = Vt + (size_t)bh*L_*HD_;

    auto loadK = [&](int i, int stage){
        const __half* src = Kg + (size_t)i*64*HD_;
        uint32_t base = ksb + (uint32_t)stage*(64*FLDH*2);
        #pragma unroll
        for (int p=0;p<4;p++){
            int idx = tid + p*256;        // 1024 chunks of 8 halves
            int r = idx >> 4, c8 = (idx & 15)*8;
            cpa16(base + (uint32_t)(r*FLDH + c8)*2, src + r*HD_ + c8);
        }
        CPA_COMMIT();
    };
    auto loadV = [&](int i){
        const __half* src = Vg + (size_t)i*64*HD_;
        #pragma unroll
        for (int p=0;p<4;p++){
            int idx = tid + p*256;
            int r = idx >> 4, c8 = (idx & 15)*8;
            cpa16(vsb + (uint32_t)(r*FLDH + c8)*2, src + r*HD_ + c8);
        }
        CPA_COMMIT();
    };

    loadK(0, 0);
    loadV(0);
    loadK(1, 1);

    // Q tile via cp.async too (2048 chunks)
    #pragma unroll
    for (int p=0;p<8;p++){
        int idx = tid + p*256;
        int r = idx >> 4, c8 = (idx & 15)*8;
        cpa16(qsb + (uint32_t)(r*FLDH + c8)*2, Qg + r*HD_ + c8);
    }
    CPA_COMMIT();   // group order: K0, V0, K1, Q

    const int myr  = lane >> 1;
    const int half_ = lane & 1;
    float mrow = -1e30f, lrow = 0.f;

    wmma::fragment<wmma::accumulator,16,16,16,float> oc[8];
    #pragma unroll
    for (int j=0;j<8;j++) wmma::fill_fragment(oc[j], 0.f);

    for (int i=0; i<NIT; i++){
        // wait for K[i] (and Q on first iter).
        // groups newer than K[i]: i=0: V0,K1,Q ->0 (need Q too); i=1: Q... conservative: 0 for i<2.
        if (i < 2)       { CPA_WAIT(0); }
        else if (i < 31) { CPA_WAIT(3); }
        else             { CPA_WAIT(2); }
        __syncthreads();

        const __half* Kst = Ks + (i&1)*(64*FLDH);

        // S = Qrows x K^T (16x64 per warp)
        wmma::fragment<wmma::accumulator,16,16,16,float> sc[4];
        #pragma unroll
        for (int j=0;j<4;j++) wmma::fill_fragment(sc[j], 0.f);
        #pragma unroll
        for (int ka=0; ka<8; ka++){
            wmma::fragment<wmma::matrix_a,16,16,16,half,wmma::row_major> af;
            wmma::load_matrix_sync(af, Qs + (w*16)*FLDH + ka*16, FLDH);
            #pragma unroll
            for (int j=0;j<4;j++){
                wmma::fragment<wmma::matrix_b,16,16,16,half,wmma::col_major> bf;
                wmma::load_matrix_sync(bf, Kst + (j*16)*FLDH + ka*16, FLDH);
                wmma::mma_sync(sc[j], af, bf, sc[j]);
            }
        }
        __syncthreads();                 // all warps done reading K stage i&1
        if (i+2 < NIT) loadK(i+2, i&1);

        #pragma unroll
        for (int j=0;j<4;j++)
            wmma::store_matrix_sync(Ss + j*16, sc[j], FSLD, wmma::mem_row_major);
        __syncwarp();

        // warp-local online softmax (lane pair per row), P -> half
        float* srow = Ss + myr*FSLD + half_*32;
        __half* prow = Ps + myr*FPLD + half_*32;
        float mx = mrow;
        #pragma unroll
        for (int c=0;c<32;c++) mx = fmaxf(mx, srow[c]);
        mx = fmaxf(mx, __shfl_xor_sync(0xffffffffu, mx, 1));
        float alpha = __expf(mrow - mx);
        float sum = 0.f;
        #pragma unroll
        for (int c=0;c<32;c+=2){
            float p0 = __expf(srow[c]   - mx);
            float p1 = __expf(srow[c+1] - mx);
            sum += p0 + p1;
            *(__half2*)(prow + c) = __floats2half2_rn(p0, p1);
        }
        sum += __shfl_xor_sync(0xffffffffu, sum, 1);
        lrow = lrow*alpha + sum;
        mrow = mx;

        // rescale O fragments via alpha broadcast tile
        #pragma unroll
        for (int c=0;c<8;c++) At[myr*16 + half_*8 + c] = alpha;
        __syncwarp();
        wmma::fragment<wmma::accumulator,16,16,16,float> afr;
        wmma::load_matrix_sync(afr, At, 16, wmma::mem_row_major);
        #pragma unroll
        for (int j=0;j<8;j++)
            #pragma unroll
            for (int e=0;e<afr.num_elements;e++) oc[j].x[e] *= afr.x[e];

        // wait for V[i]
        if (i <= 29) { CPA_WAIT(1); }
        else         { CPA_WAIT(0); }
        __syncthreads();

        // O += P * V
        #pragma unroll
        for (int ka=0; ka<4; ka++){
            wmma::fragment<wmma::matrix_a,16,16,16,half,wmma::row_major> pf;
            wmma::load_matrix_sync(pf, Ps + ka*16, FPLD);
            #pragma unroll
            for (int j=0;j<8;j++){
                wmma::fragment<wmma::matrix_b,16,16,16,half,wmma::row_major> vf;
                wmma::load_matrix_sync(vf, Vs + (ka*16)*FLDH + j*16, FLDH);
                wmma::mma_sync(oc[j], pf, vf, oc[j]);
            }
        }
        __syncthreads();                 // all warps done reading Vs
        if (i+1 < NIT) loadV(i+1);
    }

    // epilogue: stage O (fp32) into smem front, normalize, write half [b,l,h,d]
    float* stg = (float*)dynsm + w*16*132;
    #pragma unroll
    for (int j=0;j<8;j++)
        wmma::store_matrix_sync(stg + j*16, oc[j], 132, wmma::mem_row_major);
    __syncwarp();
    float rl = 1.f / lrow;
    int l = qt*128 + w*16 + myr;
    __half* dst = Out + (((size_t)b*L_ + l)*H_ + h)*HD_ + half_*64;
    const float* srcr = stg + myr*132 + half_*64;
    #pragma unroll
    for (int c=0;c<16;c++){
        float4 v = *(const float4*)(srcr + c*4);
        __half2* dp = (__half2*)(dst + c*4);
        dp[0] = __floats2half2_rn(v.x*rl, v.y*rl);
        dp[1] = __floats2half2_rn(v.z*rl, v.w*rl);
    }
}

// ================================================================================
extern "C" void kernel_launch(void* const* d_in, const int* in_sizes, int n_in,
                              void* d_out, int out_size)
{
    const float* x    = (const float*)d_in[0];
    const float* cosq = (const float*)d_in[1];
    const float* sinq = (const float*)d_in[2];
    const float* cosk = (const float*)d_in[3];
    const float* sink = (const float*)d_in[4];
    const float* Wq   = (const float*)d_in[5];
    const float* Wk   = (const float*)d_in[6];
    const float* Wv   = (const float*)d_in[7];
    const float* Wo   = (const float*)d_in[8];
    const float* qg   = (const float*)d_in[9];
    const float* kg   = (const float*)d_in[10];
    float* out = (float*)d_out;

    __half *Xh, *Wh, *Qh, *Kh, *Vh, *Ah;
    cudaGetSymbolAddress((void**)&Xh, g_Xh);
    cudaGetSymbolAddress((void**)&Wh, g_Wh);
    cudaGetSymbolAddress((void**)&Qh, g_Qh);
    cudaGetSymbolAddress((void**)&Kh, g_Kh);
    cudaGetSymbolAddress((void**)&Vh, g_Vh);
    cudaGetSymbolAddress((void**)&Ah, g_Ah);

    cudaFuncSetAttribute(gemm_h, cudaFuncAttributeMaxDynamicSharedMemorySize, GSMEMH);
    cudaFuncSetAttribute(flash_h_kernel, cudaFuncAttributeMaxDynamicSharedMemorySize, FL_BYTES);

    // fp16 conversion
    tohalf_kernel<<<BL_*D_/1024, 256>>>(x,  Xh, BL_*D_);
    tohalf_kernel<<<D_*D_/1024, 256>>>(Wq, Wh + 0*(size_t)D_*D_, D_*D_);
    tohalf_kernel<<<D_*D_/1024, 256>>>(Wk, Wh + 1*(size_t)D_*D_, D_*D_);
    tohalf_kernel<<<D_*D_/1024, 256>>>(Wv, Wh + 2*(size_t)D_*D_, D_*D_);
    tohalf_kernel<<<D_*D_/1024, 256>>>(Wo, Wh + 3*(size_t)D_*D_, D_*D_);

    dim3 gg(D_/128, BL_/128);   // (16, 64)
    gemm_h<<<gg, 256, GSMEMH>>>(Xh, Wh + 0*(size_t)D_*D_, Qh, 1);
    gemm_h<<<gg, 256, GSMEMH>>>(Xh, Wh + 1*(size_t)D_*D_, Kh, 1);
    gemm_h<<<gg, 256, GSMEMH>>>(Xh, Wh + 2*(size_t)D_*D_, Vh, 1);

    normrope_h_kernel<<<(B_*H_*L_)/8, 256>>>(Qh, Kh, cosq, sinq, cosk, sink, qg, kg);

    flash_h_kernel<<<dim3(L_/128, B_*H_), 256, FL_BYTES>>>(Qh, Kh, Vh, Ah);

    gemm_h<<<gg, 256, GSMEMH>>>(Ah, Wh + 3*(size_t)D_*D_, out, 0);
}

// round 7
// speedup vs baseline: 5.2834x; 1.1657x over previous
#include <cuda_runtime.h>
#include <cuda_fp16.h>
#include <mma.h>
#include <math.h>
#include <stdint.h>

using namespace nvcuda;

#define B_   4
#define L_   2048
#define D_   2048
#define H_   16
#define HD_  128
#define BL_  (B_*L_)
#define SM_SCALE 0.08838834764831845f

__device__ __half g_Xh[BL_*D_];
__device__ __half g_Wh[4][D_*D_];
__device__ __half g_Qh[BL_*D_];
__device__ __half g_Kh[BL_*D_];
__device__ __half g_Vh[BL_*D_];
__device__ __half g_Ah[BL_*D_];

// ---------------- helpers ----------------
__device__ __forceinline__ uint32_t smem_u32(const void* p){
    uint32_t a;
    asm("{ .reg .u64 t; cvta.to.shared.u64 t, %1; cvt.u32.u64 %0, t; }":"=r"(a):"l"(p));
    return a;
}
__device__ __forceinline__ void cpa16(uint32_t dst, const void* src){
    asm volatile("cp.async.cg.shared.global [%0], [%1], 16;"::"r"(dst),"l"(src):"memory");
}
#define CPA_COMMIT() asm volatile("cp.async.commit_group;":::"memory")
#define CPA_WAIT(N)  asm volatile("cp.async.wait_group %0;"::"n"(N):"memory")

#define LDSM4(r, a) \
    asm volatile("ldmatrix.sync.aligned.m8n8.x4.shared.b16 {%0,%1,%2,%3}, [%4];" \
        : "=r"((r)[0]),"=r"((r)[1]),"=r"((r)[2]),"=r"((r)[3]) : "r"(a))
#define LDSM4T(r, a) \
    asm volatile("ldmatrix.sync.aligned.m8n8.x4.trans.shared.b16 {%0,%1,%2,%3}, [%4];" \
        : "=r"((r)[0]),"=r"((r)[1]),"=r"((r)[2]),"=r"((r)[3]) : "r"(a))
#define MMA16816(c, a, b0, b1) \
    asm volatile("mma.sync.aligned.m16n8k16.row.col.f32.f16.f16.f32 " \
        "{%0,%1,%2,%3}, {%4,%5,%6,%7}, {%8,%9}, {%0,%1,%2,%3};" \
        : "+f"((c)[0]),"+f"((c)[1]),"+f"((c)[2]),"+f"((c)[3]) \
        : "r"((a)[0]),"r"((a)[1]),"r"((a)[2]),"r"((a)[3]),"r"(b0),"r"(b1))

extern __shared__ __align__(1024) char dynsm[];

// ---------------- fp32 -> fp16 convert ----------------
__global__ __launch_bounds__(256) void tohalf_kernel(
    const float* __restrict__ s, __half* __restrict__ d, int n)
{
    int i = (blockIdx.x*256 + threadIdx.x)*4;
    if (i < n){
        float4 v = *(const float4*)(s+i);
        __half2* dp = (__half2*)(d+i);
        dp[0] = __floats2half2_rn(v.x, v.y);
        dp[1] = __floats2half2_rn(v.z, v.w);
    }
}

// ================================================================================
// Pipelined fp16 wmma GEMM (unchanged from R6 — proven)
// ================================================================================
#define GLDH 72
#define GBKH 64
#define KITH (D_/GBKH)               // 32
#define ASTGH (128*GLDH*2)           // 18432 bytes
#define STGH  (2*ASTGH)              // 36864
#define GSMEMH (3*STGH)              // 110592

__global__ __launch_bounds__(256,2) void gemm_h(
    const __half* __restrict__ A, const __half* __restrict__ W,
    void* __restrict__ Cv, int mode)
{
    __half* fs = (__half*)dynsm;
    const uint32_t smb = smem_u32(fs);
    const int tid  = threadIdx.x;
    const int warp = tid >> 5;
    const int wm   = warp >> 2;
    const int wn   = warp & 3;
    const int rowBase = blockIdx.y * 128;
    const int colBase = blockIdx.x * 128;

    wmma::fragment<wmma::accumulator,16,16,16,float> cf[4][2];
    #pragma unroll
    for (int i=0;i<4;i++)
        #pragma unroll
        for (int j=0;j<2;j++)
            wmma::fill_fragment(cf[i][j], 0.0f);

    auto load_stage = [&](int k){
        const int st = k % 3;
        const uint32_t sb = smb + (uint32_t)st*STGH;
        const int k0 = k*GBKH;
        #pragma unroll
        for (int c=0;c<8;c++){
            int idx = tid + c*256;
            int row = idx >> 3;
            int c8  = (idx & 7)*8;
            if (row < 128){
                cpa16(sb + (uint32_t)(row*GLDH + c8)*2,
                      A + (size_t)(rowBase+row)*D_ + k0 + c8);
            } else {
                int r2 = row - 128;
                cpa16(sb + ASTGH + (uint32_t)(r2*GLDH + c8)*2,
                      W + (size_t)(colBase+r2)*D_ + k0 + c8);
            }
        }
        CPA_COMMIT();
    };

    load_stage(0);
    load_stage(1);

    for (int k=0; k<KITH; k++){
        if (k+2 < KITH) load_stage(k+2);
        int rem = KITH-1-k;
        if (rem >= 2)      { CPA_WAIT(2); }
        else if (rem == 1) { CPA_WAIT(1); }
        else               { CPA_WAIT(0); }
        __syncthreads();

        const __half* As = fs + (size_t)(k%3)*STGH/2;
        const __half* Bs = As + ASTGH/2;
        #pragma unroll
        for (int kk=0; kk<4; kk++){
            wmma::fragment<wmma::matrix_b,16,16,16,half,wmma::col_major> bf[2];
            #pragma unroll
            for (int j=0;j<2;j++)
                wmma::load_matrix_sync(bf[j], Bs + (wn*32 + j*16)*GLDH + kk*16, GLDH);
            #pragma unroll
            for (int i=0;i<4;i++){
                wmma::fragment<wmma::matrix_a,16,16,16,half,wmma::row_major> af;
                wmma::load_matrix_sync(af, As + (wm*64 + i*16)*GLDH + kk*16, GLDH);
                #pragma unroll
                for (int j=0;j<2;j++)
                    wmma::mma_sync(cf[i][j], af, bf[j], cf[i][j]);
            }
        }
        __syncthreads();
    }

    if (mode == 0){
        float* C = (float*)Cv;
        #pragma unroll
        for (int i=0;i<4;i++){
            int m = rowBase + wm*64 + i*16;
            #pragma unroll
            for (int j=0;j<2;j++){
                int n = colBase + wn*32 + j*16;
                wmma::store_matrix_sync(C + (size_t)m*D_ + n, cf[i][j], D_, wmma::mem_row_major);
            }
        }
    } else {
        float* stg = (float*)dynsm;
        #pragma unroll
        for (int i=0;i<4;i++)
            #pragma unroll
            for (int j=0;j<2;j++)
                wmma::store_matrix_sync(stg + (wm*64 + i*16)*132 + wn*32 + j*16,
                                        cf[i][j], 132, wmma::mem_row_major);
        __syncthreads();
        __half* C = (__half*)Cv;
        const int hh = blockIdx.x;
        #pragma unroll
        for (int p=0;p<8;p++){
            int idx = tid + p*256;
            int r  = idx >> 4;
            int c8 = (idx & 15)*8;
            int m = rowBase + r;
            int b = m >> 11, l = m & 2047;
            const float* sr = stg + r*132 + c8;
            __half2 h0 = __floats2half2_rn(sr[0], sr[1]);
            __half2 h1 = __floats2half2_rn(sr[2], sr[3]);
            __half2 h2 = __floats2half2_rn(sr[4], sr[5]);
            __half2 h3 = __floats2half2_rn(sr[6], sr[7]);
            __half2* dst = (__half2*)(C + (((size_t)b*H_ + hh)*L_ + l)*HD_ + c8);
            dst[0]=h0; dst[1]=h1; dst[2]=h2; dst[3]=h3;
        }
    }
}

// ---------------- RMSNorm + RoPE (unchanged from R6) ----------------
__global__ __launch_bounds__(256) void normrope_h_kernel(
    __half* __restrict__ Q, __half* __restrict__ Kx,
    const float* __restrict__ cosq, const float* __restrict__ sinq,
    const float* __restrict__ cosk, const float* __restrict__ sink,
    const float* __restrict__ qg,   const float* __restrict__ kg)
{
    const unsigned FULL = 0xffffffffu;
    int gw   = (blockIdx.x*256 + threadIdx.x) >> 5;
    int lane = threadIdx.x & 31;
    int l    = gw % L_;
    int b    = gw / (H_*L_);
    int d0   = lane*4;
    size_t base  = (size_t)gw * HD_;
    size_t cbase = ((size_t)b*L_ + l)*HD_ + d0;
    float sgn = (lane < 16) ? -1.0f : 1.0f;

    {
        const __half2* hp = (const __half2*)(Q + base + d0);
        float2 a0 = __half22float2(hp[0]), a1 = __half22float2(hp[1]);
        float4 v; v.x=a0.x; v.y=a0.y; v.z=a1.x; v.w=a1.y;
        float ss = v.x*v.x + v.y*v.y + v.z*v.z + v.w*v.w;
        #pragma unroll
        for (int o=16;o;o>>=1) ss += __shfl_xor_sync(FULL, ss, o);
        float rs = rsqrtf(ss*(1.0f/128.0f) + 1e-6f);
        float4 g = *(const float4*)(qg + d0);
        float4 n; n.x=v.x*rs*g.x; n.y=v.y*rs*g.y; n.z=v.z*rs*g.z; n.w=v.w*rs*g.w;
        float4 p;
        p.x=__shfl_xor_sync(FULL,n.x,16); p.y=__shfl_xor_sync(FULL,n.y,16);
        p.z=__shfl_xor_sync(FULL,n.z,16); p.w=__shfl_xor_sync(FULL,n.w,16);
        float4 c = *(const float4*)(cosq + cbase);
        float4 s = *(const float4*)(sinq + cbase);
        __half2* dp = (__half2*)(Q + base + d0);
        dp[0] = __floats2half2_rn((n.x*c.x + sgn*p.x*s.x)*SM_SCALE,
                                  (n.y*c.y + sgn*p.y*s.y)*SM_SCALE);
        dp[1] = __floats2half2_rn((n.z*c.z + sgn*p.z*s.z)*SM_SCALE,
                                  (n.w*c.w + sgn*p.w*s.w)*SM_SCALE);
    }
    {
        const __half2* hp = (const __half2*)(Kx + base + d0);
        float2 a0 = __half22float2(hp[0]), a1 = __half22float2(hp[1]);
        float4 v; v.x=a0.x; v.y=a0.y; v.z=a1.x; v.w=a1.y;
        float ss = v.x*v.x + v.y*v.y + v.z*v.z + v.w*v.w;
        #pragma unroll
        for (int o=16;o;o>>=1) ss += __shfl_xor_sync(FULL, ss, o);
        float rs = rsqrtf(ss*(1.0f/128.0f) + 1e-6f);
        float4 g = *(const float4*)(kg + d0);
        float4 n; n.x=v.x*rs*g.x; n.y=v.y*rs*g.y; n.z=v.z*rs*g.z; n.w=v.w*rs*g.w;
        float4 p;
        p.x=__shfl_xor_sync(FULL,n.x,16); p.y=__shfl_xor_sync(FULL,n.y,16);
        p.z=__shfl_xor_sync(FULL,n.z,16); p.w=__shfl_xor_sync(FULL,n.w,16);
        float4 c = *(const float4*)(cosk + cbase);
        float4 s = *(const float4*)(sink + cbase);
        __half2* dp = (__half2*)(Kx + base + d0);
        dp[0] = __floats2half2_rn(n.x*c.x + sgn*p.x*s.x,
                                  n.y*c.y + sgn*p.y*s.y);
        dp[1] = __floats2half2_rn(n.z*c.z + sgn*p.z*s.z,
                                  n.w*c.w + sgn*p.w*s.w);
    }
}

// ================================================================================
// flash3: raw mma.sync m16n8k16, register-resident S/P/O, warp-local softmax.
// BQ=128 (8 warps x 16 rows), BKT=64, K double-buffered, V prefetch.
// ================================================================================
#define NIT  (L_/64)          // 32
#define FLDH 136
#define F3_QS 0
#define F3_KS 34816                       // 128*136*2
#define F3_KSTG 17408                     // 64*136*2
#define F3_VS (F3_KS + 2*F3_KSTG)         // 69632
#define F3_BYTES (F3_VS + F3_KSTG)        // 87040

__global__ __launch_bounds__(256) void flash3_kernel(
    const __half* __restrict__ Q, const __half* __restrict__ Kt,
    const __half* __restrict__ Vt, __half* __restrict__ Out)
{
    const uint32_t smb = smem_u32(dynsm);
    const uint32_t qsb = smb + F3_QS;
    const uint32_t ksb = smb + F3_KS;
    const uint32_t vsb = smb + F3_VS;
    const int tid = threadIdx.x, w = tid>>5, lane = tid&31;

    const int bh = blockIdx.y, qt = blockIdx.x;
    const int b = bh >> 4, h = bh & 15;
    const __half* Qg = Q  + ((size_t)bh*L_ + qt*128)*HD_;
    const __half* Kg = Kt + (size_t)bh*L_*HD_;
    const __half* Vg = Vt + (size_t)bh*L_*HD_;

    auto loadK = [&](int i, int stage){
        const __half* src = Kg + (size_t)i*64*HD_;
        uint32_t base = ksb + (uint32_t)stage*F3_KSTG;
        #pragma unroll
        for (int p=0;p<4;p++){
            int idx = tid + p*256;
            int r = idx >> 4, c8 = (idx & 15)*8;
            cpa16(base + (uint32_t)(r*FLDH + c8)*2, src + r*HD_ + c8);
        }
        CPA_COMMIT();
    };
    auto loadV = [&](int i){
        const __half* src = Vg + (size_t)i*64*HD_;
        #pragma unroll
        for (int p=0;p<4;p++){
            int idx = tid + p*256;
            int r = idx >> 4, c8 = (idx & 15)*8;
            cpa16(vsb + (uint32_t)(r*FLDH + c8)*2, src + r*HD_ + c8);
        }
        CPA_COMMIT();
    };

    loadK(0, 0);
    loadV(0);
    loadK(1, 1);
    #pragma unroll
    for (int p=0;p<8;p++){
        int idx = tid + p*256;
        int r = idx >> 4, c8 = (idx & 15)*8;
        cpa16(qsb + (uint32_t)(r*FLDH + c8)*2, Qg + r*HD_ + c8);
    }
    CPA_COMMIT();          // groups: K0, V0, K1, Q
    CPA_WAIT(0);
    __syncthreads();

    // Q A-fragments, loaded once: q[ka][0..3], ka = d 16-block
    uint32_t q[8][4];
    {
        uint32_t qa = qsb + (uint32_t)((w*16 + (lane&15))*FLDH + (lane>>4)*8)*2;
        #pragma unroll
        for (int ka=0; ka<8; ka++)
            LDSM4(q[ka], qa + (uint32_t)(ka*16)*2);
    }

    // O accumulators: 16 m16n8 tiles covering d=0..127
    float oc[16][4];
    #pragma unroll
    for (int t=0;t<16;t++){ oc[t][0]=0.f; oc[t][1]=0.f; oc[t][2]=0.f; oc[t][3]=0.f; }
    float mrow0 = -1e30f, mrow1 = -1e30f, lrow0 = 0.f, lrow1 = 0.f;

    // precomputed ldmatrix lane-offset pieces (elements)
    const uint32_t kofs = (uint32_t)(((lane&7) + (lane>>4)*8)*FLDH + ((lane>>3)&1)*8);
    const uint32_t vofs = (uint32_t)(((lane&7) + ((lane>>3)&1)*8)*FLDH + (lane>>4)*8);

    for (int i=0; i<NIT; i++){
        if (i < 31) { CPA_WAIT(3); }
        else        { CPA_WAIT(2); }
        __syncthreads();

        const uint32_t kst = ksb + (uint32_t)(i&1)*F3_KSTG;

        // ---- S = Q K^T : 8 tiles of 16x8 in registers ----
        float sc[8][4];
        #pragma unroll
        for (int t=0;t<8;t++){ sc[t][0]=0.f; sc[t][1]=0.f; sc[t][2]=0.f; sc[t][3]=0.f; }
        #pragma unroll
        for (int ka=0; ka<8; ka++){
            #pragma unroll
            for (int nt=0; nt<4; nt++){
                uint32_t kb[4];
                LDSM4(kb, kst + (uint32_t)(nt*16*FLDH + ka*16 + kofs)*2);
                MMA16816(sc[2*nt],   q[ka], kb[0], kb[1]);
                MMA16816(sc[2*nt+1], q[ka], kb[2], kb[3]);
            }
        }
        __syncthreads();                 // all warps done with K stage i&1
        if (i+2 < NIT) loadK(i+2, i&1);

        // ---- warp-local softmax in registers ----
        float mx0 = mrow0, mx1 = mrow1;
        #pragma unroll
        for (int t=0;t<8;t++){
            mx0 = fmaxf(mx0, fmaxf(sc[t][0], sc[t][1]));
            mx1 = fmaxf(mx1, fmaxf(sc[t][2], sc[t][3]));
        }
        mx0 = fmaxf(mx0, __shfl_xor_sync(0xffffffffu, mx0, 1));
        mx0 = fmaxf(mx0, __shfl_xor_sync(0xffffffffu, mx0, 2));
        mx1 = fmaxf(mx1, __shfl_xor_sync(0xffffffffu, mx1, 1));
        mx1 = fmaxf(mx1, __shfl_xor_sync(0xffffffffu, mx1, 2));
        float alpha0 = __expf(mrow0 - mx0);
        float alpha1 = __expf(mrow1 - mx1);
        float sum0 = 0.f, sum1 = 0.f;
        uint32_t pa[4][4];               // A-fragments for PV (keys 16j..16j+15)
        #pragma unroll
        for (int t=0;t<8;t++){
            float p0 = __expf(sc[t][0] - mx0);
            float p1 = __expf(sc[t][1] - mx0);
            float p2 = __expf(sc[t][2] - mx1);
            float p3 = __expf(sc[t][3] - mx1);
            sum0 += p0 + p1;
            sum1 += p2 + p3;
            __half2 h01 = __floats2half2_rn(p0, p1);
            __half2 h23 = __floats2half2_rn(p2, p3);
            int j = t >> 1;
            if ((t & 1) == 0){
                pa[j][0] = *(uint32_t*)&h01;  // a0: rows g,   k 0-7
                pa[j][1] = *(uint32_t*)&h23;  // a1: rows g+8, k 0-7
            } else {
                pa[j][2] = *(uint32_t*)&h01;  // a2: rows g,   k 8-15
                pa[j][3] = *(uint32_t*)&h23;  // a3: rows g+8, k 8-15
            }
        }
        sum0 += __shfl_xor_sync(0xffffffffu, sum0, 1);
        sum0 += __shfl_xor_sync(0xffffffffu, sum0, 2);
        sum1 += __shfl_xor_sync(0xffffffffu, sum1, 1);
        sum1 += __shfl_xor_sync(0xffffffffu, sum1, 2);
        lrow0 = lrow0*alpha0 + sum0;  mrow0 = mx0;
        lrow1 = lrow1*alpha1 + sum1;  mrow1 = mx1;

        // rescale O
        #pragma unroll
        for (int t=0;t<16;t++){
            oc[t][0] *= alpha0; oc[t][1] *= alpha0;
            oc[t][2] *= alpha1; oc[t][3] *= alpha1;
        }

        // ---- wait for V[i], then O += P V ----
        if (i <= 29) { CPA_WAIT(1); }
        else         { CPA_WAIT(0); }
        __syncthreads();

        #pragma unroll
        for (int j=0;j<4;j++){
            #pragma unroll
            for (int db=0; db<8; db++){
                uint32_t vb[4];
                LDSM4T(vb, vsb + (uint32_t)(j*16*FLDH + db*16 + vofs)*2);
                MMA16816(oc[2*db],   pa[j], vb[0], vb[1]);
                MMA16816(oc[2*db+1], pa[j], vb[2], vb[3]);
            }
        }
        __syncthreads();                 // all warps done with Vs
        if (i+1 < NIT) loadV(i+1);
    }

    // ---- epilogue: normalize and write half [b,l,h,d] directly from regs ----
    float rl0 = 1.f / lrow0;
    float rl1 = 1.f / lrow1;
    int l0 = qt*128 + w*16 + (lane>>2);
    __half* base0 = Out + (((size_t)b*L_ + l0    )*H_ + h)*HD_;
    __half* base1 = Out + (((size_t)b*L_ + l0 + 8)*H_ + h)*HD_;
    #pragma unroll
    for (int t=0;t<16;t++){
        int d = t*8 + (lane&3)*2;
        *(__half2*)(base0 + d) = __floats2half2_rn(oc[t][0]*rl0, oc[t][1]*rl0);
        *(__half2*)(base1 + d) = __floats2half2_rn(oc[t][2]*rl1, oc[t][3]*rl1);
    }
}

// ================================================================================
extern "C" void kernel_launch(void* const* d_in, const int* in_sizes, int n_in,
                              void* d_out, int out_size)
{
    const float* x    = (const float*)d_in[0];
    const float* cosq = (const float*)d_in[1];
    const float* sinq = (const float*)d_in[2];
    const float* cosk = (const float*)d_in[3];
    const float* sink = (const float*)d_in[4];
    const float* Wq   = (const float*)d_in[5];
    const float* Wk   = (const float*)d_in[6];
    const float* Wv   = (const float*)d_in[7];
    const float* Wo   = (const float*)d_in[8];
    const float* qg   = (const float*)d_in[9];
    const float* kg   = (const float*)d_in[10];
    float* out = (float*)d_out;

    __half *Xh, *Wh, *Qh, *Kh, *Vh, *Ah;
    cudaGetSymbolAddress((void**)&Xh, g_Xh);
    cudaGetSymbolAddress((void**)&Wh, g_Wh);
    cudaGetSymbolAddress((void**)&Qh, g_Qh);
    cudaGetSymbolAddress((void**)&Kh, g_Kh);
    cudaGetSymbolAddress((void**)&Vh, g_Vh);
    cudaGetSymbolAddress((void**)&Ah, g_Ah);

    cudaFuncSetAttribute(gemm_h, cudaFuncAttributeMaxDynamicSharedMemorySize, GSMEMH);
    cudaFuncSetAttribute(flash3_kernel, cudaFuncAttributeMaxDynamicSharedMemorySize, F3_BYTES);

    tohalf_kernel<<<BL_*D_/1024, 256>>>(x,  Xh, BL_*D_);
    tohalf_kernel<<<D_*D_/1024, 256>>>(Wq, Wh + 0*(size_t)D_*D_, D_*D_);
    tohalf_kernel<<<D_*D_/1024, 256>>>(Wk, Wh + 1*(size_t)D_*D_, D_*D_);
    tohalf_kernel<<<D_*D_/1024, 256>>>(Wv, Wh + 2*(size_t)D_*D_, D_*D_);
    tohalf_kernel<<<D_*D_/1024, 256>>>(Wo, Wh + 3*(size_t)D_*D_, D_*D_);

    dim3 gg(D_/128, BL_/128);   // (16, 64)
    gemm_h<<<gg, 256, GSMEMH>>>(Xh, Wh + 0*(size_t)D_*D_, Qh, 1);
    gemm_h<<<gg, 256, GSMEMH>>>(Xh, Wh + 1*(size_t)D_*D_, Kh, 1);
    gemm_h<<<gg, 256, GSMEMH>>>(Xh, Wh + 2*(size_t)D_*D_, Vh, 1);

    normrope_h_kernel<<<(B_*H_*L_)/8, 256>>>(Qh, Kh, cosq, sinq, cosk, sink, qg, kg);

    flash3_kernel<<<dim3(L_/128, B_*H_), 256, F3_BYTES>>>(Qh, Kh, Vh, Ah);

    gemm_h<<<gg, 256, GSMEMH>>>(Ah, Wh + 3*(size_t)D_*D_, out, 0);
}